// round 3
// baseline (speedup 1.0000x reference)
#include <cuda_runtime.h>
#include <math.h>

// Problem constants
#define BB   256    // graphs
#define NN   2048   // nodes
#define RR   64     // roots
#define DD   64     // embed dim
#define TT   8      // node types
#define KD   128    // K*D (MLP input)
#define HH   128    // hidden (2D)
#define LMAX 64     // level cap (actual max depth ~35; fallback kernel covers >=LMAX)
#define TM   64     // rows per GEMM tile
#define XPITCH 132  // smem row pitch (floats), multiple of 4

// ---------------- device scratch (static, no allocation) ----------------
__device__ int           g_cnt[LMAX * TT];
__device__ int           g_start[LMAX * TT + 1];
__device__ int           g_cursor[LMAX * TT];
__device__ unsigned char g_lvl[BB * NN];
__device__ unsigned int  g_list[BB * (NN - RR)];

__device__ __forceinline__ float gelu_exact(float v) {
    return 0.5f * v * (1.0f + erff(v * 0.70710678118654752f));
}

// ---------------- K0: zero counters ----------------
__global__ void k_zero() {
    g_cnt[threadIdx.x] = 0;   // 1 block, 512 threads
}

// ---------------- K_roots: copy root embeddings into out[:, :R, :] ----------------
__global__ void k_roots(const float4* __restrict__ roots, float4* __restrict__ out) {
    int e = blockIdx.x * blockDim.x + threadIdx.x;   // total 256*64*64/4 = 262144
    int b = e >> 10;            // RR*DD/4 = 1024 float4 per graph
    int rem = e & 1023;
    out[(size_t)b * ((NN * DD) >> 2) + rem] = roots[e];
}

// ---------------- K1: per-graph level computation + histogram ----------------
__global__ void k_levels(const int* __restrict__ idxs, const int* __restrict__ types) {
    __shared__ int   sIdx[NN * 2];      // 16KB
    __shared__ short sLvl[NN];          // 4KB
    __shared__ int   sHist[LMAX * TT];  // 2KB
    int b = blockIdx.x, tid = threadIdx.x;

    for (int e = tid; e < NN * 2; e += 256) sIdx[e] = idxs[b * NN * 2 + e];
    for (int e = tid; e < NN; e += 256)     sLvl[e] = 0;
    for (int e = tid; e < LMAX * TT; e += 256) sHist[e] = 0;
    __syncthreads();

    // warp 0: fixpoint iteration per 32-node window (parents < i, so windows sequential)
    if (tid < 32) {
        volatile short* vl = sLvl;
        for (int base = RR; base < NN; base += 32) {
            int i = base + tid;
            int p0 = sIdx[2 * i], p1 = sIdx[2 * i + 1];
            while (true) {
                int l0 = vl[p0], l1 = vl[p1];
                int nl = 1 + (l0 > l1 ? l0 : l1);
                int ch = (nl != (int)vl[i]);
                __syncwarp();
                vl[i] = (short)nl;
                __syncwarp();
                if (!__ballot_sync(0xffffffffu, ch)) break;
            }
        }
    }
    __syncthreads();

    for (int e = RR + tid; e < NN; e += 256) {
        int L = sLvl[e];
        g_lvl[b * NN + e] = (unsigned char)(L < 255 ? L : 255);
        if (L < LMAX) atomicAdd(&sHist[L * TT + types[b * NN + e]], 1);
    }
    __syncthreads();
    for (int e = tid; e < LMAX * TT; e += 256)
        if (sHist[e]) atomicAdd(&g_cnt[e], sHist[e]);
}

// ---------------- K2: exclusive prefix scan over 512 buckets ----------------
__global__ void k_scan() {
    __shared__ int s[512];
    int tid = threadIdx.x;
    int v = g_cnt[tid];
    s[tid] = v;
    __syncthreads();
    for (int off = 1; off < 512; off <<= 1) {
        int x = (tid >= off) ? s[tid - off] : 0;
        __syncthreads();
        s[tid] += x;
        __syncthreads();
    }
    int excl = s[tid] - v;
    g_start[tid]  = excl;
    g_cursor[tid] = excl;
    if (tid == 511) g_start[512] = s[511];
}

// ---------------- K3: scatter (b,i) into (level,type) buckets ----------------
__global__ void k_scatter(const int* __restrict__ types) {
    int b = blockIdx.x, tid = threadIdx.x;
    for (int e = RR + tid; e < NN; e += 256) {
        int L = g_lvl[b * NN + e];
        if (L < LMAX) {
            int t = types[b * NN + e];
            int pos = atomicAdd(&g_cursor[L * TT + t], 1);
            g_list[pos] = ((unsigned)b << 11) | (unsigned)e;
        }
    }
}

// ---------------- K4: per-level tiled GEMM compute ----------------
__global__ void __launch_bounds__(256)
k_level(const float* __restrict__ W1, const float* __restrict__ bias1,
        const float* __restrict__ W2, const float* __restrict__ bias2,
        const int* __restrict__ idxs, float* __restrict__ out, int L) {
    __shared__ float        sbuf[TM * XPITCH];  // x tile, then reused for h tile (~33.8KB)
    __shared__ unsigned int sV[TM];
    __shared__ int          sP[2][TM];
    __shared__ int          sMeta[9];

    int tid = threadIdx.x;
    if (tid < 9) sMeta[tid] = g_start[L * TT + tid];
    __syncthreads();

    int tx = tid & 31, ty = tid >> 5;
    int tg = blockIdx.x;

    for (int t = 0; t < TT; t++) {
        int base = sMeta[t];
        int cnt  = sMeta[t + 1] - base;
        int nt   = (cnt + TM - 1) / TM;
        while (tg < nt) {
            int rowBase = base + tg * TM;
            int rows = cnt - tg * TM; if (rows > TM) rows = TM;

            __syncthreads();  // protect sbuf/sV reuse across tiles
            if (tid < TM) {
                if (tid < rows) {
                    unsigned int v = g_list[rowBase + tid];
                    sV[tid] = v;
                    sP[0][tid] = idxs[2 * v];
                    sP[1][tid] = idxs[2 * v + 1];
                } else { sV[tid] = 0; sP[0][tid] = 0; sP[1][tid] = 0; }
            }
            __syncthreads();

            // gather parent embeddings -> sbuf[r][0:128]
            {
                const float4* outv = (const float4*)out;
                for (int e = tid; e < TM * 32; e += 256) {
                    int r = e >> 5, q = e & 31, which = q >> 4, seg = q & 15;
                    int p = sP[which][r];
                    unsigned int b = sV[r] >> 11;
                    float4 vv = outv[((size_t)b * NN + p) * 16 + seg];
                    *(float4*)&sbuf[r * XPITCH + which * 64 + seg * 4] = vv;
                }
            }
            __syncthreads();

            // GEMM1: h[64][128] = x @ W1[t] + b1[t]
            float acc[8][4];
            {
                const float* bb = bias1 + t * HH + tx * 4;
                float c0 = bb[0], c1 = bb[1], c2 = bb[2], c3 = bb[3];
                #pragma unroll
                for (int rr = 0; rr < 8; rr++) {
                    acc[rr][0] = c0; acc[rr][1] = c1; acc[rr][2] = c2; acc[rr][3] = c3;
                }
            }
            {
                const float4* w1v = (const float4*)W1 + (size_t)(t * KD) * 32 + tx;
                const float* xb = &sbuf[(ty * 8) * XPITCH];
                #pragma unroll 4
                for (int k = 0; k < KD; k += 4) {
                    float xv[8][4];
                    #pragma unroll
                    for (int rr = 0; rr < 8; rr++) {
                        float4 tmp = *(const float4*)(xb + rr * XPITCH + k);
                        xv[rr][0] = tmp.x; xv[rr][1] = tmp.y; xv[rr][2] = tmp.z; xv[rr][3] = tmp.w;
                    }
                    #pragma unroll
                    for (int j = 0; j < 4; j++) {
                        float4 w = w1v[(k + j) * 32];
                        #pragma unroll
                        for (int rr = 0; rr < 8; rr++) {
                            float xs = xv[rr][j];
                            acc[rr][0] = fmaf(xs, w.x, acc[rr][0]);
                            acc[rr][1] = fmaf(xs, w.y, acc[rr][1]);
                            acc[rr][2] = fmaf(xs, w.z, acc[rr][2]);
                            acc[rr][3] = fmaf(xs, w.w, acc[rr][3]);
                        }
                    }
                }
            }
            __syncthreads();  // all x reads done before overwriting sbuf with h

            #pragma unroll
            for (int rr = 0; rr < 8; rr++) {
                float4 g;
                g.x = gelu_exact(acc[rr][0]);
                g.y = gelu_exact(acc[rr][1]);
                g.z = gelu_exact(acc[rr][2]);
                g.w = gelu_exact(acc[rr][3]);
                *(float4*)&sbuf[(ty * 8 + rr) * XPITCH + tx * 4] = g;
            }
            __syncthreads();

            // GEMM2: out[64][64] = h @ W2[t] + b2[t]
            float a2[8][2];
            {
                float c0 = bias2[t * DD + tx * 2];
                float c1 = bias2[t * DD + tx * 2 + 1];
                #pragma unroll
                for (int rr = 0; rr < 8; rr++) { a2[rr][0] = c0; a2[rr][1] = c1; }
            }
            {
                const float2* w2v = (const float2*)W2 + (size_t)(t * KD) * 32 + tx;
                const float* hb = &sbuf[(ty * 8) * XPITCH];
                #pragma unroll 4
                for (int k = 0; k < KD; k += 4) {
                    float hv[8][4];
                    #pragma unroll
                    for (int rr = 0; rr < 8; rr++) {
                        float4 tmp = *(const float4*)(hb + rr * XPITCH + k);
                        hv[rr][0] = tmp.x; hv[rr][1] = tmp.y; hv[rr][2] = tmp.z; hv[rr][3] = tmp.w;
                    }
                    #pragma unroll
                    for (int j = 0; j < 4; j++) {
                        float2 w = w2v[(k + j) * 32];
                        #pragma unroll
                        for (int rr = 0; rr < 8; rr++) {
                            a2[rr][0] = fmaf(hv[rr][j], w.x, a2[rr][0]);
                            a2[rr][1] = fmaf(hv[rr][j], w.y, a2[rr][1]);
                        }
                    }
                }
            }
            {
                float2* out2 = (float2*)out;
                #pragma unroll
                for (int rr = 0; rr < 8; rr++) {
                    int r = ty * 8 + rr;
                    if (r < rows) {
                        float2 st; st.x = a2[rr][0]; st.y = a2[rr][1];
                        out2[(size_t)sV[r] * 32 + tx] = st;
                    }
                }
            }
            tg += gridDim.x;
        }
        tg -= nt;
    }
}

// ---------------- K5: sequential fallback for nodes with level >= LMAX ----------------
__global__ void k_cleanup(const float* __restrict__ W1, const float* __restrict__ bias1,
                          const float* __restrict__ W2, const float* __restrict__ bias2,
                          const int* __restrict__ idxs, const int* __restrict__ types,
                          float* __restrict__ out) {
    __shared__ int   sAny;
    __shared__ float sx[KD];
    __shared__ float sh[HH];
    int b = blockIdx.x, tid = threadIdx.x;  // 128 threads
    if (tid == 0) sAny = 0;
    __syncthreads();
    for (int e = RR + tid; e < NN; e += 128)
        if (g_lvl[b * NN + e] >= LMAX) sAny = 1;
    __syncthreads();
    if (!sAny) return;

    for (int i = RR; i < NN; i++) {
        if (g_lvl[b * NN + i] < LMAX) continue;
        int t = types[b * NN + i];
        int which = tid >> 6;
        int p = idxs[(b * NN + i) * 2 + which];
        sx[tid] = out[((size_t)b * NN + p) * DD + (tid & 63)];
        __syncthreads();
        {
            float a = bias1[t * HH + tid];
            for (int kk = 0; kk < KD; kk++)
                a = fmaf(sx[kk], W1[(size_t)(t * KD + kk) * HH + tid], a);
            sh[tid] = gelu_exact(a);
        }
        __syncthreads();
        if (tid < DD) {
            float a = bias2[t * DD + tid];
            for (int kk = 0; kk < HH; kk++)
                a = fmaf(sh[kk], W2[(size_t)(t * KD + kk) * DD + tid], a);
            out[((size_t)b * NN + i) * DD + tid] = a;
        }
        __syncthreads();
    }
}

// ---------------- launch ----------------
extern "C" void kernel_launch(void* const* d_in, const int* in_sizes, int n_in,
                              void* d_out, int out_size) {
    const float* roots = (const float*)d_in[0];   // [B,R,D]
    const float* W1    = (const float*)d_in[1];   // [T,128,128]
    const float* b1    = (const float*)d_in[2];   // [T,128]
    const float* W2    = (const float*)d_in[3];   // [T,128,64]
    const float* b2    = (const float*)d_in[4];   // [T,64]
    const int*   idxs  = (const int*)d_in[5];     // [B,N,2]
    const int*   types = (const int*)d_in[6];     // [B,N]
    float* out = (float*)d_out;                   // [B,N,D]

    k_zero<<<1, 512>>>();
    k_roots<<<(BB * RR * DD / 4) / 256, 256>>>((const float4*)roots, (float4*)out);
    k_levels<<<BB, 256>>>(idxs, types);
    k_scan<<<1, 512>>>();
    k_scatter<<<BB, 256>>>(types);
    for (int L = 1; L < LMAX; L++) {
        k_level<<<304, 256>>>(W1, b1, W2, b2, idxs, out, L);
    }
    k_cleanup<<<BB, 128>>>(W1, b1, W2, b2, idxs, types, out);
}